// round 16
// baseline (speedup 1.0000x reference)
#include <cuda_runtime.h>
#include <cstdint>

// ---------------- problem constants ----------------
#define BATCH   32
#define CH      512
#define HW      3136
#define NCL     27
#define TOTPX   (BATCH * HW)
#define PROBS_ELEMS (BATCH * NCL * HW)

#define MTILE   128                 // pixels per tile
#define TILES_PER_B 25              // ceil(3136/128), last tile 64 valid
#define NTILES  (BATCH * TILES_PER_B)   // 800
#define TPB     128
#define OCC     5
#define CCH     16                  // channels per chunk (2 K-steps of 8)
#define NCHUNKS (CH / CCH)          // 32
#define NPADN   32                  // clusters padded to 32

// ---------------- smem: 4-stage cp.async ring, distance-3 prefetch ----------------
#define XS_STRIDE  136                              // floats, conflict-free frags
#define XSTG_BYTES (CCH * XS_STRIDE * 4)            // 8704 (x raw)
#define SB_STRIDE  20                               // floats; conflict-free
#define BSTG_BYTES (NPADN * SB_STRIDE * 4)          // 2560 (B raw clusters)
#define STG_BYTES  (XSTG_BYTES + BSTG_BYTES)        // 11264
#define STAGES     4
#define DIST       3                                // prefetch distance (chunks)
#define RING_BYTES (STAGES * STG_BYTES)             // 45056
#define SSIM_STRIDE 132
#define SSS_OFF    (NPADN * SSIM_STRIDE * 4)        // 16896 (fits in ring)
#define SMEM_BYTES RING_BYTES                       // 45056 static

// ---------------- device scratch ----------------
__device__ double g_accum;             // zero-init; self-resetting
__device__ int    g_done;              // CTA completion ticket (self-resetting)

// ---------------- helpers ----------------
__device__ __forceinline__ float tf32_rna(float x) {
    uint32_t u;
    asm("cvt.rna.tf32.f32 %0, %1;" : "=r"(u) : "f"(x));
    return __uint_as_float(u);
}
__device__ __forceinline__ void mma_tf32(float* d, const uint32_t* a, const uint32_t* b) {
    asm volatile(
        "mma.sync.aligned.m16n8k8.row.col.f32.tf32.tf32.f32 "
        "{%0,%1,%2,%3}, {%4,%5,%6,%7}, {%8,%9}, {%0,%1,%2,%3};"
        : "+f"(d[0]), "+f"(d[1]), "+f"(d[2]), "+f"(d[3])
        : "r"(a[0]), "r"(a[1]), "r"(a[2]), "r"(a[3]), "r"(b[0]), "r"(b[1]));
}
__device__ __forceinline__ void cp16(uint32_t dst, const void* src, int nbytes) {
    asm volatile("cp.async.cg.shared.global [%0], [%1], 16, %2;"
                 :: "r"(dst), "l"(src), "r"(nbytes) : "memory");
}
#define CP_COMMIT()  asm volatile("cp.async.commit_group;" ::: "memory")
#define CP_WAIT2()   asm volatile("cp.async.wait_group 2;" ::: "memory")
#define CP_WAIT0()   asm volatile("cp.async.wait_group 0;" ::: "memory")

// ---------------- single fused kernel ----------------
__global__ void __launch_bounds__(TPB, OCC)
cluster_main(const float* __restrict__ x, const float* __restrict__ clusters,
             float* __restrict__ probs, float* __restrict__ loss) {
    __shared__ __align__(16) char sm[SMEM_BYTES];
    __shared__ float sred[4];
    __shared__ float s_csum[NPADN];    // cluster sum-of-squares
    __shared__ float s_icv[NPADN];     // 1/max(||c||, eps)

    const int tid  = threadIdx.x;
    const int lane = tid & 31;
    const int warp = tid >> 5;
    const uint32_t smb = (uint32_t)__cvta_generic_to_shared(sm);
    const int wpx = warp * 32;

    const int g    = blockIdx.x;
    const int b    = g / TILES_PER_B;
    const int tile = g % TILES_PER_B;
    const int pix  = tile * MTILE + tid;
    const bool valid = (pix < HW);
    const float* xtile = x + (size_t)b * CH * HW + tile * MTILE;

    const bool seg_ok = (tile * MTILE + lane * 4 + 4 <= HW);
    const int xbytes = seg_ok ? 16 : 0;

    // x cp.async byte offsets: 4 transfers, channels warp+4i
    uint32_t xoff[4];
    #pragma unroll
    for (int i = 0; i < 4; ++i)
        xoff[i] = (uint32_t)(warp + 4 * i) * (XS_STRIDE * 4) + lane * 16;

    // B cp.async: 128 threads x 1 transfer = 32 rows x 4 segs (16B each), RAW clusters
    const int brow = tid >> 2;
    const int bseg = tid & 3;
    const int brow_c = (brow < NCL) ? brow : 0;     // clamp pad rows (cols 27-31 of D unused)
    const uint32_t boff = XSTG_BYTES + brow * (SB_STRIDE * 4) + bseg * 16;

    // fragment byte offsets within a stage (k-step 0; k-step 1 adds 8 floats)
    int fo[2], bo[4];
    #pragma unroll
    for (int mt = 0; mt < 2; ++mt)
        fo[mt] = ((lane & 3) * XS_STRIDE + wpx + mt * 16 + (lane >> 2)) * 4;
    #pragma unroll
    for (int nt = 0; nt < 4; ++nt)
        bo[nt] = XSTG_BYTES + ((nt * 8 + (lane >> 2)) * SB_STRIDE + (lane & 3)) * 4;

    // incremental producer state
    const float* xsrc = xtile + (size_t)warp * HW + lane * 4;
    const float* bsrc = clusters + (size_t)brow_c * CH + bseg * 4;
    uint32_t wbase = smb;
    auto issue = [&]() {
        #pragma unroll
        for (int i = 0; i < 4; ++i)
            cp16(wbase + xoff[i],
                 seg_ok ? (const void*)(xsrc + (size_t)(4 * i) * HW)
                        : (const void*)xtile, xbytes);
        cp16(wbase + boff, bsrc, 16);
        xsrc += (size_t)CCH * HW;
        bsrc += CCH;
        wbase += STG_BYTES;
        if (wbase == smb + RING_BYTES) wbase = smb;
    };

    float d[2][4][4];
    #pragma unroll
    for (int mt = 0; mt < 2; ++mt)
        #pragma unroll
        for (int nt = 0; nt < 4; ++nt)
            #pragma unroll
            for (int i = 0; i < 4; ++i) d[mt][nt][i] = 0.0f;
    float ssr[2][2] = {{0.f, 0.f}, {0.f, 0.f}};
    float ssb[4] = {0.f, 0.f, 0.f, 0.f};   // cluster row sum-of-squares (partial)

    // prime DIST=3 stages
    #pragma unroll
    for (int p = 0; p < DIST; ++p) { issue(); CP_COMMIT(); }

    uint32_t rbase = smb;
    for (int kc = 0; kc < NCHUNKS; ++kc) {
        CP_WAIT2();          // chunk-kc group complete (3 outstanding -> 2)
        __syncthreads();     // all warps' chunk-kc data visible; all past kc-1
        if (kc + DIST < NCHUNKS) issue();   // writes slot (kc-1)%4: safe post-barrier
        CP_COMMIT();         // unconditional: group-count invariant in tail

        const char* sbase = (const char*)sm + (rbase - smb);
        #pragma unroll
        for (int ks = 0; ks < 2; ++ks) {    // two K=8 steps per chunk
            const int ka = ks * 8 * XS_STRIDE * 4;   // A: +8 k-rows
            const int kb = ks * 8 * 4;               // B: +8 floats in-row
            uint32_t ah[2][4], bh[4][2];
            #pragma unroll
            for (int mt = 0; mt < 2; ++mt) {
                const float* xp = (const float*)(sbase + fo[mt] + ka);
                const float r0 = xp[0];
                const float r1 = xp[8];
                const float r2 = xp[4 * XS_STRIDE];
                const float r3 = xp[4 * XS_STRIDE + 8];
                ssr[mt][0] = fmaf(r0, r0, fmaf(r2, r2, ssr[mt][0]));
                ssr[mt][1] = fmaf(r1, r1, fmaf(r3, r3, ssr[mt][1]));
                ah[mt][0] = __float_as_uint(tf32_rna(r0));
                ah[mt][1] = __float_as_uint(tf32_rna(r1));
                ah[mt][2] = __float_as_uint(tf32_rna(r2));
                ah[mt][3] = __float_as_uint(tf32_rna(r3));
            }
            #pragma unroll
            for (int nt = 0; nt < 4; ++nt) {
                const float* bp = (const float*)(sbase + bo[nt] + kb);
                const float b0 = bp[0], b4 = bp[4];
                ssb[nt] = fmaf(b0, b0, fmaf(b4, b4, ssb[nt]));
                bh[nt][0] = __float_as_uint(tf32_rna(b0));
                bh[nt][1] = __float_as_uint(tf32_rna(b4));
            }
            #pragma unroll
            for (int mt = 0; mt < 2; ++mt)
                #pragma unroll
                for (int nt = 0; nt < 4; ++nt)
                    mma_tf32(d[mt][nt], ah[mt], bh[nt]);
        }

        rbase += STG_BYTES;
        if (rbase == smb + RING_BYTES) rbase = smb;
    }

    // drain outstanding cp.async (targets overlap epilogue region), then reuse ring
    CP_WAIT0();
    __syncthreads();

    // ---- epilogue (ring smem reused) ----
    float* ssim = (float*)sm;                 // [32][132]
    float* sss  = (float*)(sm + SSS_OFF);     // [128]
    #pragma unroll
    for (int mt = 0; mt < 2; ++mt) {
        const int r0 = wpx + mt * 16 + (lane >> 2);
        #pragma unroll
        for (int nt = 0; nt < 4; ++nt) {
            const int n0 = nt * 8 + (lane & 3) * 2;
            ssim[n0 * SSIM_STRIDE + r0]           = d[mt][nt][0];
            ssim[(n0 + 1) * SSIM_STRIDE + r0]     = d[mt][nt][1];
            ssim[n0 * SSIM_STRIDE + r0 + 8]       = d[mt][nt][2];
            ssim[(n0 + 1) * SSIM_STRIDE + r0 + 8] = d[mt][nt][3];
        }
    }
    // pixel ||x||^2: quad-reduce ssr
    #pragma unroll
    for (int mt = 0; mt < 2; ++mt)
        #pragma unroll
        for (int j = 0; j < 2; ++j) {
            float vv = ssr[mt][j];
            vv += __shfl_xor_sync(0xffffffffu, vv, 1);
            vv += __shfl_xor_sync(0xffffffffu, vv, 2);
            if ((lane & 3) == 0)
                sss[wpx + mt * 16 + j * 8 + (lane >> 2)] = vv;
        }
    // cluster ||c||^2: each warp holds full sums; warp 0 publishes
    if (warp == 0) {
        #pragma unroll
        for (int nt = 0; nt < 4; ++nt) {
            float vv = ssb[nt];
            vv += __shfl_xor_sync(0xffffffffu, vv, 1);
            vv += __shfl_xor_sync(0xffffffffu, vv, 2);
            if ((lane & 3) == 0)
                s_csum[nt * 8 + (lane >> 2)] = vv;
        }
    }
    __syncthreads();
    if (tid < NCL)
        s_icv[tid] = 1.0f / fmaxf(sqrtf(s_csum[tid]), 1e-12f);
    __syncthreads();

    const float inv = 1.0f / fmaxf(sqrtf(sss[tid]), 1e-12f);
    float sims[NCL], m = -1e30f;
    #pragma unroll
    for (int n = 0; n < NCL; ++n) {
        sims[n] = ssim[n * SSIM_STRIDE + tid] * inv * s_icv[n];
        m = fmaxf(m, sims[n]);
    }
    float se = 0.0f, ses = 0.0f;
    #pragma unroll
    for (int n = 0; n < NCL; ++n) {
        const float e = __expf(2.0f * (sims[n] - m));
        se += e; ses += e * sims[n];
        sims[n] = e;
    }
    const float r = 1.0f / se;

    if (probs != nullptr && valid) {
        float* op = probs + (size_t)b * NCL * HW + pix;
        #pragma unroll
        for (int n = 0; n < NCL; ++n) __stcs(op + (size_t)n * HW, sims[n] * r);
    }

    // ---- loss reduction ----
    float c = valid ? (ses * r) : 0.0f;
    #pragma unroll
    for (int o = 16; o > 0; o >>= 1) c += __shfl_xor_sync(0xffffffffu, c, o);
    if (lane == 0) sred[warp] = c;
    __syncthreads();
    if (tid == 0)
        atomicAdd(&g_accum, (double)(sred[0] + sred[1] + sred[2] + sred[3]));

    // ---- fused finalize: last CTA writes loss, resets state for next replay ----
    if (tid == 0) {
        __threadfence();
        const int t = atomicAdd(&g_done, 1);
        if (t == NTILES - 1) {
            if (loss != nullptr) *loss = (float)(-g_accum / (double)TOTPX);
            g_accum = 0.0;
            g_done  = 0;
        }
    }
}

extern "C" void kernel_launch(void* const* d_in, const int* in_sizes, int n_in,
                              void* d_out, int out_size) {
    const float* x        = (const float*)d_in[0];
    const float* clusters = (const float*)d_in[1];
    float* out = (float*)d_out;

    float* probs_ptr = nullptr;
    float* loss_ptr  = nullptr;
    if (out_size >= PROBS_ELEMS) {
        probs_ptr = out + (out_size - PROBS_ELEMS);
        if (out_size > PROBS_ELEMS) loss_ptr = out;
    } else {
        loss_ptr = out;
    }

    cluster_main<<<NTILES, TPB>>>(x, clusters, probs_ptr, loss_ptr);
}

// round 17
// speedup vs baseline: 1.1919x; 1.1919x over previous
#include <cuda_runtime.h>
#include <cstdint>

// ---------------- problem constants ----------------
#define BATCH   32
#define CH      512
#define HW      3136
#define NCL     27
#define TOTPX   (BATCH * HW)
#define PROBS_ELEMS (BATCH * NCL * HW)

#define MTILE   128                 // pixels per tile
#define TILES_PER_B 25              // ceil(3136/128), last tile 64 valid
#define NTILES  (BATCH * TILES_PER_B)   // 800
#define TPB     128
#define OCC     5
#define CCH     16                  // channels per chunk (2 K-steps of 8)
#define NCHUNKS (CH / CCH)          // 32
#define NPADN   32                  // clusters padded to 32 (rows 27-31 zero)

// ---------------- smem: 4-stage cp.async ring, distance-3 prefetch ----------------
#define XS_STRIDE  136                              // floats, conflict-free frags
#define XSTG_BYTES (CCH * XS_STRIDE * 4)            // 8704 (x raw)
#define SB_STRIDE  20                               // floats; conflict-free
#define BSTG_BYTES (NPADN * SB_STRIDE * 4)          // 2560 (B tf32-rna)
#define STG_BYTES  (XSTG_BYTES + BSTG_BYTES)        // 11264
#define STAGES     4
#define DIST       3                                // prefetch distance (chunks)
#define RING_BYTES (STAGES * STG_BYTES)             // 45056
#define SSIM_STRIDE 132
#define SSS_OFF    (NPADN * SSIM_STRIDE * 4)        // 16896 (fits in ring)
#define SMEM_BYTES RING_BYTES                       // 45056 static (< 48K)

// ---------------- device scratch ----------------
__device__ float  g_nhi[NPADN * CH];   // rna(tf32) normalized clusters, pad rows zero
__device__ double g_accum;
__device__ int    g_done;              // CTA completion ticket

// ---------------- helpers ----------------
__device__ __forceinline__ float tf32_rna(float x) {
    uint32_t u;
    asm("cvt.rna.tf32.f32 %0, %1;" : "=r"(u) : "f"(x));
    return __uint_as_float(u);
}
__device__ __forceinline__ void mma_tf32(float* d, const uint32_t* a, const uint32_t* b) {
    asm volatile(
        "mma.sync.aligned.m16n8k8.row.col.f32.tf32.tf32.f32 "
        "{%0,%1,%2,%3}, {%4,%5,%6,%7}, {%8,%9}, {%0,%1,%2,%3};"
        : "+f"(d[0]), "+f"(d[1]), "+f"(d[2]), "+f"(d[3])
        : "r"(a[0]), "r"(a[1]), "r"(a[2]), "r"(a[3]), "r"(b[0]), "r"(b[1]));
}
__device__ __forceinline__ void cp16(uint32_t dst, const void* src, int nbytes) {
    asm volatile("cp.async.cg.shared.global [%0], [%1], 16, %2;"
                 :: "r"(dst), "l"(src), "r"(nbytes) : "memory");
}
#define CP_COMMIT()  asm volatile("cp.async.commit_group;" ::: "memory")
#define CP_WAIT2()   asm volatile("cp.async.wait_group 2;" ::: "memory")
#define CP_WAIT0()   asm volatile("cp.async.wait_group 0;" ::: "memory")

// ---------------- Kernel A: normalize clusters, rna-rounded (PDL primary) ----------------
__global__ void normalize_clusters(const float* __restrict__ clusters) {
    cudaTriggerProgrammaticLaunchCompletion();   // let cluster_main start launching now
    __shared__ float swarp[8];
    const int n = blockIdx.x;
    const int tid = threadIdx.x, lane = tid & 31, w = tid >> 5;
    if (n >= NCL) {       // pad block: zero rows 27-31, reset accum + ticket
        for (int i = tid; i < (NPADN - NCL) * CH; i += 256) g_nhi[NCL * CH + i] = 0.0f;
        if (tid == 0) { g_accum = 0.0; g_done = 0; }
        return;
    }
    const float* row = clusters + (size_t)n * CH;
    float ss = 0.0f;
    for (int c = tid; c < CH; c += 256) { float v = row[c]; ss += v * v; }
    #pragma unroll
    for (int o = 16; o > 0; o >>= 1) ss += __shfl_xor_sync(0xffffffffu, ss, o);
    if (lane == 0) swarp[w] = ss;
    __syncthreads();
    if (tid == 0) {
        float t = 0.0f;
        #pragma unroll
        for (int i = 0; i < 8; ++i) t += swarp[i];
        swarp[0] = t;
    }
    __syncthreads();
    const float inv = 1.0f / fmaxf(sqrtf(swarp[0]), 1e-12f);
    for (int c = tid; c < CH; c += 256)
        g_nhi[n * CH + c] = tf32_rna(row[c] * inv);
}

// ---------------- Kernel B: tf32 HMMA, 4-stage distance-3, CCH=16 (PDL secondary) ----------------
__global__ void __launch_bounds__(TPB, OCC)
cluster_main(const float* __restrict__ x, float* __restrict__ probs,
             float* __restrict__ loss) {
    __shared__ __align__(16) char sm[SMEM_BYTES];
    __shared__ float sred[4];

    const int tid  = threadIdx.x;
    const int lane = tid & 31;
    const int warp = tid >> 5;
    const uint32_t smb = (uint32_t)__cvta_generic_to_shared(sm);
    const int wpx = warp * 32;

    const int g    = blockIdx.x;
    const int b    = g / TILES_PER_B;
    const int tile = g % TILES_PER_B;
    const int pix  = tile * MTILE + tid;
    const bool valid = (pix < HW);
    const float* xtile = x + (size_t)b * CH * HW + tile * MTILE;

    const bool seg_ok = (tile * MTILE + lane * 4 + 4 <= HW);
    const int xbytes = seg_ok ? 16 : 0;

    // x cp.async byte offsets: 4 transfers, channels warp+4i
    uint32_t xoff[4];
    #pragma unroll
    for (int i = 0; i < 4; ++i)
        xoff[i] = (uint32_t)(warp + 4 * i) * (XS_STRIDE * 4) + lane * 16;

    // B staging: 128 threads x 1 x 16B = 32 rows x 4 segs
    const int brow = tid >> 2;
    const int bseg = tid & 3;
    const uint32_t boff = XSTG_BYTES + brow * (SB_STRIDE * 4) + bseg * 16;

    // fragment byte offsets within a stage (k-step 0; k-step 1 adds 8 floats)
    int fo[2], bo[4];
    #pragma unroll
    for (int mt = 0; mt < 2; ++mt)
        fo[mt] = ((lane & 3) * XS_STRIDE + wpx + mt * 16 + (lane >> 2)) * 4;
    #pragma unroll
    for (int nt = 0; nt < 4; ++nt)
        bo[nt] = XSTG_BYTES + ((nt * 8 + (lane >> 2)) * SB_STRIDE + (lane & 3)) * 4;

    // ---- producers ----
    const float* xsrc = xtile + (size_t)warp * HW + lane * 4;
    uint32_t wbase = smb;
    auto issueX = [&]() {      // x only (g_nhi-independent)
        #pragma unroll
        for (int i = 0; i < 4; ++i)
            cp16(wbase + xoff[i],
                 seg_ok ? (const void*)(xsrc + (size_t)(4 * i) * HW)
                        : (const void*)xtile, xbytes);
        xsrc += (size_t)CCH * HW;
    };
    const float* bsrc = nullptr;   // set after grid sync
    auto issueXB = [&]() {     // steady-state: x + B for the same slot
        issueX();
        cp16(wbase + boff, bsrc, 16);
        bsrc += CCH;
        wbase += STG_BYTES;
        if (wbase == smb + RING_BYTES) wbase = smb;
    };

    float d[2][4][4];
    #pragma unroll
    for (int mt = 0; mt < 2; ++mt)
        #pragma unroll
        for (int nt = 0; nt < 4; ++nt)
            #pragma unroll
            for (int i = 0; i < 4; ++i) d[mt][nt][i] = 0.0f;
    float ssr[2][2] = {{0.f, 0.f}, {0.f, 0.f}};

    // 1) prime x for DIST=3 stages (overlaps with normalize_clusters via PDL)
    #pragma unroll
    for (int p = 0; p < DIST; ++p) {
        issueX();
        wbase += STG_BYTES;        // advance slot (B for these comes via LDG below)
        CP_COMMIT();
    }

    // 2) wait for normalize_clusters completion (g_nhi ready)
    cudaGridDependencySynchronize();

    // 3) one-time B staging for slots 0..2 via direct LDG+STS (L2-hot, off steady path)
    #pragma unroll
    for (int p = 0; p < DIST; ++p) {
        const float4 v = *(const float4*)(g_nhi + (size_t)brow * CH + p * CCH + bseg * 4);
        *(float4*)(sm + p * STG_BYTES + boff) = v;     // published by kc=0 barrier
    }
    bsrc = g_nhi + (size_t)brow * CH + DIST * CCH + bseg * 4;

    uint32_t rbase = smb;
    for (int kc = 0; kc < NCHUNKS; ++kc) {
        CP_WAIT2();          // chunk-kc x group complete (3 outstanding -> 2)
        __syncthreads();     // all warps' chunk-kc data (incl. STS B) visible
        if (kc + DIST < NCHUNKS) issueXB();   // writes slot (kc-1)%4: safe post-barrier
        CP_COMMIT();         // unconditional: group-count invariant in tail

        const char* sbase = (const char*)sm + (rbase - smb);
        #pragma unroll
        for (int ks = 0; ks < 2; ++ks) {    // two K=8 steps per chunk
            const int ka = ks * 8 * XS_STRIDE * 4;   // A: +8 k-rows
            const int kb = ks * 8 * 4;               // B: +8 floats in-row
            uint32_t ah[2][4], bh[4][2];
            #pragma unroll
            for (int mt = 0; mt < 2; ++mt) {
                const float* xp = (const float*)(sbase + fo[mt] + ka);
                const float r0 = xp[0];
                const float r1 = xp[8];
                const float r2 = xp[4 * XS_STRIDE];
                const float r3 = xp[4 * XS_STRIDE + 8];
                ssr[mt][0] = fmaf(r0, r0, fmaf(r2, r2, ssr[mt][0]));
                ssr[mt][1] = fmaf(r1, r1, fmaf(r3, r3, ssr[mt][1]));
                ah[mt][0] = __float_as_uint(tf32_rna(r0));
                ah[mt][1] = __float_as_uint(tf32_rna(r1));
                ah[mt][2] = __float_as_uint(tf32_rna(r2));
                ah[mt][3] = __float_as_uint(tf32_rna(r3));
            }
            #pragma unroll
            for (int nt = 0; nt < 4; ++nt) {
                const float* bp = (const float*)(sbase + bo[nt] + kb);
                bh[nt][0] = __float_as_uint(bp[0]);
                bh[nt][1] = __float_as_uint(bp[4]);
            }
            #pragma unroll
            for (int mt = 0; mt < 2; ++mt)
                #pragma unroll
                for (int nt = 0; nt < 4; ++nt)
                    mma_tf32(d[mt][nt], ah[mt], bh[nt]);
        }

        rbase += STG_BYTES;
        if (rbase == smb + RING_BYTES) rbase = smb;
    }

    // drain outstanding cp.async (targets overlap epilogue region), then reuse ring
    CP_WAIT0();
    __syncthreads();

    // ---- epilogue (ring smem reused) ----
    float* ssim = (float*)sm;                 // [32][132]
    float* sss  = (float*)(sm + SSS_OFF);     // [128]
    #pragma unroll
    for (int mt = 0; mt < 2; ++mt) {
        const int r0 = wpx + mt * 16 + (lane >> 2);
        #pragma unroll
        for (int nt = 0; nt < 4; ++nt) {
            const int n0 = nt * 8 + (lane & 3) * 2;
            ssim[n0 * SSIM_STRIDE + r0]           = d[mt][nt][0];
            ssim[(n0 + 1) * SSIM_STRIDE + r0]     = d[mt][nt][1];
            ssim[n0 * SSIM_STRIDE + r0 + 8]       = d[mt][nt][2];
            ssim[(n0 + 1) * SSIM_STRIDE + r0 + 8] = d[mt][nt][3];
        }
    }
    #pragma unroll
    for (int mt = 0; mt < 2; ++mt)
        #pragma unroll
        for (int j = 0; j < 2; ++j) {
            float vv = ssr[mt][j];
            vv += __shfl_xor_sync(0xffffffffu, vv, 1);
            vv += __shfl_xor_sync(0xffffffffu, vv, 2);
            if ((lane & 3) == 0)
                sss[wpx + mt * 16 + j * 8 + (lane >> 2)] = vv;
        }
    __syncthreads();

    const float inv = 1.0f / fmaxf(sqrtf(sss[tid]), 1e-12f);
    float sims[NCL], m = -1e30f;
    #pragma unroll
    for (int n = 0; n < NCL; ++n) {
        sims[n] = ssim[n * SSIM_STRIDE + tid] * inv;
        m = fmaxf(m, sims[n]);
    }
    float se = 0.0f, ses = 0.0f;
    #pragma unroll
    for (int n = 0; n < NCL; ++n) {
        const float e = __expf(2.0f * (sims[n] - m));
        se += e; ses += e * sims[n];
        sims[n] = e;
    }
    const float r = 1.0f / se;

    if (probs != nullptr && valid) {
        float* op = probs + (size_t)b * NCL * HW + pix;
        #pragma unroll
        for (int n = 0; n < NCL; ++n) __stcs(op + (size_t)n * HW, sims[n] * r);
    }

    // ---- loss reduction ----
    float c = valid ? (ses * r) : 0.0f;
    #pragma unroll
    for (int o = 16; o > 0; o >>= 1) c += __shfl_xor_sync(0xffffffffu, c, o);
    if (lane == 0) sred[warp] = c;
    __syncthreads();
    if (tid == 0)
        atomicAdd(&g_accum, (double)(sred[0] + sred[1] + sred[2] + sred[3]));

    // ---- fused finalize: last CTA writes the loss ----
    if (tid == 0 && loss != nullptr) {
        __threadfence();
        const int t = atomicAdd(&g_done, 1);
        if (t == NTILES - 1)
            *loss = (float)(-g_accum / (double)TOTPX);
    }
}

extern "C" void kernel_launch(void* const* d_in, const int* in_sizes, int n_in,
                              void* d_out, int out_size) {
    const float* x        = (const float*)d_in[0];
    const float* clusters = (const float*)d_in[1];
    float* out = (float*)d_out;

    float* probs_ptr = nullptr;
    float* loss_ptr  = nullptr;
    if (out_size >= PROBS_ELEMS) {
        probs_ptr = out + (out_size - PROBS_ELEMS);
        if (out_size > PROBS_ELEMS) loss_ptr = out;
    } else {
        loss_ptr = out;
    }

    normalize_clusters<<<NCL + 1, 256>>>(clusters);

    // PDL launch: cluster_main may begin while normalize_clusters runs;
    // cudaGridDependencySynchronize() inside gates the g_nhi reads.
    cudaLaunchConfig_t cfg = {};
    cfg.gridDim  = dim3(NTILES, 1, 1);
    cfg.blockDim = dim3(TPB, 1, 1);
    cudaLaunchAttribute attr[1];
    attr[0].id = cudaLaunchAttributeProgrammaticStreamSerialization;
    attr[0].val.programmaticStreamSerializationAllowed = 1;
    cfg.attrs = attr;
    cfg.numAttrs = 1;
    cudaLaunchKernelEx(&cfg, cluster_main, x, probs_ptr, loss_ptr);
}